// round 15
// baseline (speedup 1.0000x reference)
#include <cuda_runtime.h>
#include <cuda_fp16.h>
#include <cstdint>

#define N_NODES 100000
#define N_EDGES 1600000
#define IN_C 128
#define OUT_C 128
#define CAP 128                     // bucket capacity per node (deg ~ Poisson(32))

// GEMM tiling: each GEMM-role block processes 4 M=64 tiles (M=256/block)
#define GEMM_M_TILE 64
#define GEMM_TILES ((N_NODES + GEMM_M_TILE - 1) / GEMM_M_TILE)  // 1563
#define TILES_PER_BLOCK 4
#define GEMM_BLOCKS ((GEMM_TILES + TILES_PER_BLOCK - 1) / TILES_PER_BLOCK)  // 391

#define FILL_EPT 2
#define FILL_THREADS 256
#define FILL_BLOCKS (N_EDGES / (FILL_THREADS * FILL_EPT))       // 3125 exact
#define FUSED_BLOCKS (GEMM_BLOCKS + FILL_BLOCKS)                // 3516
// interleave: every 9th block is GEMM -> ceil(3516/9) = 391 exactly

#define WT_PAD 8
#define WT_LD (IN_C + WT_PAD)   // 136 halves row stride

// ---- scratch in __device__ globals (no cudaMalloc allowed) ----
__device__ __half g_xwh[(size_t)N_NODES * OUT_C]; // 25.6 MB; unscaled, then scaled in-place
__device__ float  g_dinv[N_NODES];
__device__ int    g_cursor[N_NODES];              // zeroed; fill bumps -> deg
__device__ int    g_col[(size_t)N_NODES * CAP];   // 51.2 MB bucketed adjacency

__device__ __forceinline__ unsigned h2_to_u32(__half2 h) {
    return *reinterpret_cast<unsigned*>(&h);
}

// ------------------------------------------------------------------
__global__ void k_zero_cursor() {
    int i = blockIdx.x * blockDim.x + threadIdx.x;
    if (i < N_NODES) g_cursor[i] = 0;
}

// ------------------------------------------------------------------
// Fused GEMM (unscaled fp16 out, 4 M-tiles per block) + one-pass bucketed fill.
__global__ __launch_bounds__(256, 4) void k_gemm_fill(const float* __restrict__ x,
                                                      const float* __restrict__ W,
                                                      const int* __restrict__ ei) {
    const int bid = blockIdx.x;
    const bool is_gemm = (bid % 9 == 0);

    if (!is_gemm) {
        // ---------------- fill role: one-pass bucket insert ----------------
        const int fill_id = bid - bid / 9 - 1;
        int e = (fill_id * FILL_THREADS + threadIdx.x) * FILL_EPT;
        if (e + 1 < N_EDGES) {
            int a0 = ei[e],     b0 = ei[N_EDGES + e];
            int a1 = ei[e + 1], b1 = ei[N_EDGES + e + 1];
            int p0 = atomicAdd(&g_cursor[a0], 1);
            int p1 = atomicAdd(&g_cursor[b0], 1);
            int p2 = atomicAdd(&g_cursor[a1], 1);
            int p3 = atomicAdd(&g_cursor[b1], 1);
            if (p0 < CAP) g_col[(size_t)a0 * CAP + p0] = b0;
            if (p1 < CAP) g_col[(size_t)b0 * CAP + p1] = a0;
            if (p2 < CAP) g_col[(size_t)a1 * CAP + p2] = b1;
            if (p3 < CAP) g_col[(size_t)b1 * CAP + p3] = a1;
        } else if (e < N_EDGES) {
            int a = ei[e];
            int b = ei[N_EDGES + e];
            int pa = atomicAdd(&g_cursor[a], 1);
            int pb = atomicAdd(&g_cursor[b], 1);
            if (pa < CAP) g_col[(size_t)a * CAP + pa] = b;
            if (pb < CAP) g_col[(size_t)b * CAP + pb] = a;
        }
        return;
    }

    // ---------------- GEMM role: stage W once, run 4 M=64 tiles ----------------
    __shared__ __half wt[OUT_C][WT_LD];   // W^T: wt[n][k]
    const int gemm_blk = bid / 9;
    const int tid  = threadIdx.x;
    const int wid  = tid >> 5;            // 0..7
    const int lane = tid & 31;

    for (int i = tid; i < IN_C * OUT_C; i += 256) {
        int k = i >> 7;
        int n = i & 127;
        wt[n][k] = __float2half(W[(size_t)k * OUT_C + n]);
    }
    __syncthreads();

    const int m_tile  = wid >> 1;          // 0..3
    const int n_half  = (wid & 1) * 64;    // 0 or 64
    const int qr = lane >> 2;
    const int qc = lane & 3;

    for (int t = 0; t < TILES_PER_BLOCK; t++) {
        const int gemm_id = gemm_blk * TILES_PER_BLOCK + t;
        if (gemm_id >= GEMM_TILES) break;

        const int row_base = gemm_id * GEMM_M_TILE + m_tile * 16;
        const int r0 = row_base + qr;
        const int r1 = r0 + 8;
        const int r0c = (r0 < N_NODES) ? r0 : (N_NODES - 1);
        const int r1c = (r1 < N_NODES) ? r1 : (N_NODES - 1);
        const float* xr0 = x + (size_t)r0c * IN_C;
        const float* xr1 = x + (size_t)r1c * IN_C;

        float acc[8][4];
        #pragma unroll
        for (int nt = 0; nt < 8; nt++)
            #pragma unroll
            for (int q = 0; q < 4; q++) acc[nt][q] = 0.0f;

        #pragma unroll
        for (int ks = 0; ks < IN_C / 16; ks++) {
            const int k0 = ks * 16 + qc * 2;
            float2 f;
            f = *(const float2*)(xr0 + k0);     unsigned a0 = h2_to_u32(__float22half2_rn(f));
            f = *(const float2*)(xr1 + k0);     unsigned a1 = h2_to_u32(__float22half2_rn(f));
            f = *(const float2*)(xr0 + k0 + 8); unsigned a2 = h2_to_u32(__float22half2_rn(f));
            f = *(const float2*)(xr1 + k0 + 8); unsigned a3 = h2_to_u32(__float22half2_rn(f));

            #pragma unroll
            for (int nt = 0; nt < 8; nt++) {
                const int n = n_half + nt * 8 + qr;
                unsigned b0 = *(const unsigned*)&wt[n][k0];
                unsigned b1 = *(const unsigned*)&wt[n][k0 + 8];
                asm volatile(
                    "mma.sync.aligned.m16n8k16.row.col.f32.f16.f16.f32 "
                    "{%0,%1,%2,%3}, {%4,%5,%6,%7}, {%8,%9}, {%0,%1,%2,%3};\n"
                    : "+f"(acc[nt][0]), "+f"(acc[nt][1]), "+f"(acc[nt][2]), "+f"(acc[nt][3])
                    : "r"(a0), "r"(a1), "r"(a2), "r"(a3), "r"(b0), "r"(b1));
            }
        }

        #pragma unroll
        for (int nt = 0; nt < 8; nt++) {
            const int n = n_half + nt * 8 + qc * 2;
            if (r0 < N_NODES) {
                __half2 h = __floats2half2_rn(acc[nt][0], acc[nt][1]);
                *(__half2*)(g_xwh + (size_t)r0 * OUT_C + n) = h;
            }
            if (r1 < N_NODES) {
                __half2 h = __floats2half2_rn(acc[nt][2], acc[nt][3]);
                *(__half2*)(g_xwh + (size_t)r1 * OUT_C + n) = h;
            }
        }
    }
}

// ------------------------------------------------------------------
// scale pass: dinv[n] = rsqrt(deg+1); xwh[n] *= dinv[n] in place (fp16 RMW).
__global__ void k_scale() {
    const int gid  = blockIdx.x * blockDim.x + threadIdx.x;
    const int node = gid >> 5;
    const int lane = gid & 31;
    if (node >= N_NODES) return;

    const int d = g_cursor[node];
    const float dv = rsqrtf((float)d + 1.0f);
    if (lane == 0) g_dinv[node] = dv;

    uint2* p = (uint2*)(g_xwh + (size_t)node * OUT_C) + lane;
    uint2 u = *p;
    float2 f0 = __half22float2(*(const __half2*)&u.x);
    float2 f1 = __half22float2(*(const __half2*)&u.y);
    __half2 h0 = __floats2half2_rn(f0.x * dv, f0.y * dv);
    __half2 h1 = __floats2half2_rn(f1.x * dv, f1.y * dv);
    u.x = h2_to_u32(h0);
    u.y = h2_to_u32(h1);
    *p = u;
}

// ------------------------------------------------------------------
// gather SpMM + self-loop + bias. One warp per destination node.
// int4 index loads + pairwise fp16 pre-add to cut issue count.
__global__ void k_gather(const float* __restrict__ b, float* __restrict__ y) {
    const int node = (blockIdx.x * blockDim.x + threadIdx.x) >> 5;
    const int lane = threadIdx.x & 31;
    if (node >= N_NODES) return;

    int len = g_cursor[node];
    if (len > CAP) len = CAP;
    const int beg = node * CAP;
    const int end = beg + len;

    float ax = 0.f, ay = 0.f, az = 0.f, aw = 0.f;

    int j = beg;
    for (; j + 8 <= end; j += 8) {
        const int4 ia = *(const int4*)(g_col + j);
        const int4 ib = *(const int4*)(g_col + j + 4);
        uint2 u0 = ((const uint2*)(g_xwh + (size_t)ia.x * OUT_C))[lane];
        uint2 u1 = ((const uint2*)(g_xwh + (size_t)ia.y * OUT_C))[lane];
        uint2 u2 = ((const uint2*)(g_xwh + (size_t)ia.z * OUT_C))[lane];
        uint2 u3 = ((const uint2*)(g_xwh + (size_t)ia.w * OUT_C))[lane];
        uint2 u4 = ((const uint2*)(g_xwh + (size_t)ib.x * OUT_C))[lane];
        uint2 u5 = ((const uint2*)(g_xwh + (size_t)ib.y * OUT_C))[lane];
        uint2 u6 = ((const uint2*)(g_xwh + (size_t)ib.z * OUT_C))[lane];
        uint2 u7 = ((const uint2*)(g_xwh + (size_t)ib.w * OUT_C))[lane];

        // pairwise fp16 pre-add (one rounding on a 2-message sum)
        __half2 p0 = __hadd2(*(const __half2*)&u0.x, *(const __half2*)&u1.x);
        __half2 q0 = __hadd2(*(const __half2*)&u0.y, *(const __half2*)&u1.y);
        __half2 p1 = __hadd2(*(const __half2*)&u2.x, *(const __half2*)&u3.x);
        __half2 q1 = __hadd2(*(const __half2*)&u2.y, *(const __half2*)&u3.y);
        __half2 p2 = __hadd2(*(const __half2*)&u4.x, *(const __half2*)&u5.x);
        __half2 q2 = __hadd2(*(const __half2*)&u4.y, *(const __half2*)&u5.y);
        __half2 p3 = __hadd2(*(const __half2*)&u6.x, *(const __half2*)&u7.x);
        __half2 q3 = __hadd2(*(const __half2*)&u6.y, *(const __half2*)&u7.y);

        #define ACCP(p, q) { \
            float2 f0 = __half22float2(p); \
            float2 f1 = __half22float2(q); \
            ax += f0.x; ay += f0.y; az += f1.x; aw += f1.y; }
        ACCP(p0, q0) ACCP(p1, q1) ACCP(p2, q2) ACCP(p3, q3)
        #undef ACCP
    }
    #define ACCUM(u) { \
        float2 f0 = __half22float2(*(const __half2*)&(u).x); \
        float2 f1 = __half22float2(*(const __half2*)&(u).y); \
        ax += f0.x; ay += f0.y; az += f1.x; aw += f1.y; }
    for (; j < end; j++) {
        const int c = g_col[j];
        uint2 u = ((const uint2*)(g_xwh + (size_t)c * OUT_C))[lane];
        ACCUM(u)
    }
    // self-loop (prescaled row)
    {
        uint2 u = ((const uint2*)(g_xwh + (size_t)node * OUT_C))[lane];
        ACCUM(u)
    }
    #undef ACCUM

    const float dn = g_dinv[node];
    const float4 bv = ((const float4*)b)[lane];
    float4 o;
    o.x = dn * ax + bv.x;
    o.y = dn * ay + bv.y;
    o.z = dn * az + bv.z;
    o.w = dn * aw + bv.w;
    ((float4*)(y + (size_t)node * OUT_C))[lane] = o;
}

// ------------------------------------------------------------------
extern "C" void kernel_launch(void* const* d_in, const int* in_sizes, int n_in,
                              void* d_out, int out_size) {
    const float* x  = (const float*)d_in[0];
    const float* W  = (const float*)d_in[1];
    const float* b  = (const float*)d_in[2];
    const int*   ei = (const int*)d_in[3];
    float* y = (float*)d_out;

    // zero bucket cursors
    k_zero_cursor<<<(N_NODES + 255) / 256, 256>>>();

    // fused tensor-core GEMM (4 tiles/block) + one-pass bucketed fill
    k_gemm_fill<<<FUSED_BLOCKS, 256>>>(x, W, ei);

    // dinv + in-place fp16 prescale
    k_scale<<<(N_NODES * 32 + 255) / 256, 256>>>();

    // fused gather + self-loop + bias: one warp per node
    const int gather_blocks = (N_NODES * 32 + 255) / 256;
    k_gather<<<gather_blocks, 256>>>(b, y);
}

// round 16
// speedup vs baseline: 1.0656x; 1.0656x over previous
#include <cuda_runtime.h>
#include <cuda_fp16.h>
#include <cstdint>

#define N_NODES 100000
#define N_EDGES 1600000
#define IN_C 128
#define OUT_C 128
#define CAP 128                     // bucket capacity per node (deg ~ Poisson(32))

// GEMM tiling: each GEMM-role block processes 2 M=64 tiles
#define GEMM_M_TILE 64
#define GEMM_TILES ((N_NODES + GEMM_M_TILE - 1) / GEMM_M_TILE)  // 1563
#define TILES_PER_BLOCK 2
#define GEMM_BLOCKS ((GEMM_TILES + TILES_PER_BLOCK - 1) / TILES_PER_BLOCK)  // 782

#define FILL_EPT 2
#define FILL_THREADS 256
#define FILL_BLOCKS (N_EDGES / (FILL_THREADS * FILL_EPT))       // 3125 exact
#define FUSED_BLOCKS (GEMM_BLOCKS + FILL_BLOCKS)                // 3907
// interleave: every 5th block is GEMM -> ceil(3907/5) = 782 exactly

#define WT_PAD 8
#define WT_LD (IN_C + WT_PAD)   // 136 halves row stride

// ---- scratch in __device__ globals (no cudaMalloc allowed) ----
__device__ __half g_xwh[(size_t)N_NODES * OUT_C]; // 25.6 MB; unscaled, then scaled in-place
__device__ float  g_dinv[N_NODES];
__device__ int    g_cursor[N_NODES];              // zeroed; fill bumps -> deg
__device__ int    g_col[(size_t)N_NODES * CAP];   // 51.2 MB bucketed adjacency

__device__ __forceinline__ unsigned h2_to_u32(__half2 h) {
    return *reinterpret_cast<unsigned*>(&h);
}

// ------------------------------------------------------------------
__global__ void k_zero_cursor() {
    int i = blockIdx.x * blockDim.x + threadIdx.x;
    if (i < N_NODES) g_cursor[i] = 0;
}

// ------------------------------------------------------------------
// Fused GEMM (unscaled fp16 out, 2 M-tiles per block) + one-pass bucketed fill.
__global__ __launch_bounds__(256, 4) void k_gemm_fill(const float* __restrict__ x,
                                                      const float* __restrict__ W,
                                                      const int* __restrict__ ei) {
    const int bid = blockIdx.x;
    const bool is_gemm = (bid % 5 == 0);

    if (!is_gemm) {
        // ---------------- fill role: one-pass bucket insert ----------------
        const int fill_id = bid - bid / 5 - 1;
        int e = (fill_id * FILL_THREADS + threadIdx.x) * FILL_EPT;
        if (e + 1 < N_EDGES) {
            int a0 = ei[e],     b0 = ei[N_EDGES + e];
            int a1 = ei[e + 1], b1 = ei[N_EDGES + e + 1];
            int p0 = atomicAdd(&g_cursor[a0], 1);
            int p1 = atomicAdd(&g_cursor[b0], 1);
            int p2 = atomicAdd(&g_cursor[a1], 1);
            int p3 = atomicAdd(&g_cursor[b1], 1);
            if (p0 < CAP) g_col[(size_t)a0 * CAP + p0] = b0;
            if (p1 < CAP) g_col[(size_t)b0 * CAP + p1] = a0;
            if (p2 < CAP) g_col[(size_t)a1 * CAP + p2] = b1;
            if (p3 < CAP) g_col[(size_t)b1 * CAP + p3] = a1;
        } else if (e < N_EDGES) {
            int a = ei[e];
            int b = ei[N_EDGES + e];
            int pa = atomicAdd(&g_cursor[a], 1);
            int pb = atomicAdd(&g_cursor[b], 1);
            if (pa < CAP) g_col[(size_t)a * CAP + pa] = b;
            if (pb < CAP) g_col[(size_t)b * CAP + pb] = a;
        }
        return;
    }

    // ---------------- GEMM role: stage W once, run 2 M=64 tiles ----------------
    __shared__ __half wt[OUT_C][WT_LD];   // W^T: wt[n][k]
    const int gemm_blk = bid / 5;
    const int tid  = threadIdx.x;
    const int wid  = tid >> 5;            // 0..7
    const int lane = tid & 31;

    for (int i = tid; i < IN_C * OUT_C; i += 256) {
        int k = i >> 7;
        int n = i & 127;
        wt[n][k] = __float2half(W[(size_t)k * OUT_C + n]);
    }
    __syncthreads();

    const int m_tile  = wid >> 1;          // 0..3
    const int n_half  = (wid & 1) * 64;    // 0 or 64
    const int qr = lane >> 2;
    const int qc = lane & 3;

    #pragma unroll
    for (int t = 0; t < TILES_PER_BLOCK; t++) {
        const int gemm_id = gemm_blk * TILES_PER_BLOCK + t;
        if (gemm_id >= GEMM_TILES) break;

        const int row_base = gemm_id * GEMM_M_TILE + m_tile * 16;
        const int r0 = row_base + qr;
        const int r1 = r0 + 8;
        const int r0c = (r0 < N_NODES) ? r0 : (N_NODES - 1);
        const int r1c = (r1 < N_NODES) ? r1 : (N_NODES - 1);
        const float* xr0 = x + (size_t)r0c * IN_C;
        const float* xr1 = x + (size_t)r1c * IN_C;

        float acc[8][4];
        #pragma unroll
        for (int nt = 0; nt < 8; nt++)
            #pragma unroll
            for (int q = 0; q < 4; q++) acc[nt][q] = 0.0f;

        #pragma unroll
        for (int ks = 0; ks < IN_C / 16; ks++) {
            const int k0 = ks * 16 + qc * 2;
            float2 f;
            f = *(const float2*)(xr0 + k0);     unsigned a0 = h2_to_u32(__float22half2_rn(f));
            f = *(const float2*)(xr1 + k0);     unsigned a1 = h2_to_u32(__float22half2_rn(f));
            f = *(const float2*)(xr0 + k0 + 8); unsigned a2 = h2_to_u32(__float22half2_rn(f));
            f = *(const float2*)(xr1 + k0 + 8); unsigned a3 = h2_to_u32(__float22half2_rn(f));

            #pragma unroll
            for (int nt = 0; nt < 8; nt++) {
                const int n = n_half + nt * 8 + qr;
                unsigned b0 = *(const unsigned*)&wt[n][k0];
                unsigned b1 = *(const unsigned*)&wt[n][k0 + 8];
                asm volatile(
                    "mma.sync.aligned.m16n8k16.row.col.f32.f16.f16.f32 "
                    "{%0,%1,%2,%3}, {%4,%5,%6,%7}, {%8,%9}, {%0,%1,%2,%3};\n"
                    : "+f"(acc[nt][0]), "+f"(acc[nt][1]), "+f"(acc[nt][2]), "+f"(acc[nt][3])
                    : "r"(a0), "r"(a1), "r"(a2), "r"(a3), "r"(b0), "r"(b1));
            }
        }

        #pragma unroll
        for (int nt = 0; nt < 8; nt++) {
            const int n = n_half + nt * 8 + qc * 2;
            if (r0 < N_NODES) {
                __half2 h = __floats2half2_rn(acc[nt][0], acc[nt][1]);
                *(__half2*)(g_xwh + (size_t)r0 * OUT_C + n) = h;
            }
            if (r1 < N_NODES) {
                __half2 h = __floats2half2_rn(acc[nt][2], acc[nt][3]);
                *(__half2*)(g_xwh + (size_t)r1 * OUT_C + n) = h;
            }
        }
    }
}

// ------------------------------------------------------------------
// scale pass: dinv[n] = rsqrt(deg+1); xwh[n] *= dinv[n] in place (fp16 RMW).
__global__ void k_scale() {
    const int gid  = blockIdx.x * blockDim.x + threadIdx.x;
    const int node = gid >> 5;
    const int lane = gid & 31;
    if (node >= N_NODES) return;

    const int d = g_cursor[node];
    const float dv = rsqrtf((float)d + 1.0f);
    if (lane == 0) g_dinv[node] = dv;

    uint2* p = (uint2*)(g_xwh + (size_t)node * OUT_C) + lane;
    uint2 u = *p;
    float2 f0 = __half22float2(*(const __half2*)&u.x);
    float2 f1 = __half22float2(*(const __half2*)&u.y);
    __half2 h0 = __floats2half2_rn(f0.x * dv, f0.y * dv);
    __half2 h1 = __floats2half2_rn(f1.x * dv, f1.y * dv);
    u.x = h2_to_u32(h0);
    u.y = h2_to_u32(h1);
    *p = u;
}

// ------------------------------------------------------------------
// gather SpMM + self-loop + bias. One warp per destination node.
// (R14 form: 8 independent scalar index loads -> incremental gather issue.)
__global__ void k_gather(const float* __restrict__ b, float* __restrict__ y) {
    const int node = (blockIdx.x * blockDim.x + threadIdx.x) >> 5;
    const int lane = threadIdx.x & 31;
    if (node >= N_NODES) return;

    int len = g_cursor[node];
    if (len > CAP) len = CAP;
    const int beg = node * CAP;
    const int end = beg + len;

    float ax = 0.f, ay = 0.f, az = 0.f, aw = 0.f;

    int j = beg;
    for (; j + 8 <= end; j += 8) {
        int c0 = g_col[j + 0], c1 = g_col[j + 1], c2 = g_col[j + 2], c3 = g_col[j + 3];
        int c4 = g_col[j + 4], c5 = g_col[j + 5], c6 = g_col[j + 6], c7 = g_col[j + 7];
        uint2 u0 = ((const uint2*)(g_xwh + (size_t)c0 * OUT_C))[lane];
        uint2 u1 = ((const uint2*)(g_xwh + (size_t)c1 * OUT_C))[lane];
        uint2 u2 = ((const uint2*)(g_xwh + (size_t)c2 * OUT_C))[lane];
        uint2 u3 = ((const uint2*)(g_xwh + (size_t)c3 * OUT_C))[lane];
        uint2 u4 = ((const uint2*)(g_xwh + (size_t)c4 * OUT_C))[lane];
        uint2 u5 = ((const uint2*)(g_xwh + (size_t)c5 * OUT_C))[lane];
        uint2 u6 = ((const uint2*)(g_xwh + (size_t)c6 * OUT_C))[lane];
        uint2 u7 = ((const uint2*)(g_xwh + (size_t)c7 * OUT_C))[lane];
        #define ACCUM(u) { \
            float2 f0 = __half22float2(*(const __half2*)&(u).x); \
            float2 f1 = __half22float2(*(const __half2*)&(u).y); \
            ax += f0.x; ay += f0.y; az += f1.x; aw += f1.y; }
        ACCUM(u0) ACCUM(u1) ACCUM(u2) ACCUM(u3)
        ACCUM(u4) ACCUM(u5) ACCUM(u6) ACCUM(u7)
    }
    for (; j < end; j++) {
        const int c = g_col[j];
        uint2 u = ((const uint2*)(g_xwh + (size_t)c * OUT_C))[lane];
        ACCUM(u)
    }
    // self-loop (prescaled row)
    {
        uint2 u = ((const uint2*)(g_xwh + (size_t)node * OUT_C))[lane];
        ACCUM(u)
    }
    #undef ACCUM

    const float dn = g_dinv[node];
    const float4 bv = ((const float4*)b)[lane];
    float4 o;
    o.x = dn * ax + bv.x;
    o.y = dn * ay + bv.y;
    o.z = dn * az + bv.z;
    o.w = dn * aw + bv.w;
    ((float4*)(y + (size_t)node * OUT_C))[lane] = o;
}

// ------------------------------------------------------------------
extern "C" void kernel_launch(void* const* d_in, const int* in_sizes, int n_in,
                              void* d_out, int out_size) {
    const float* x  = (const float*)d_in[0];
    const float* W  = (const float*)d_in[1];
    const float* b  = (const float*)d_in[2];
    const int*   ei = (const int*)d_in[3];
    float* y = (float*)d_out;

    // zero bucket cursors
    k_zero_cursor<<<(N_NODES + 255) / 256, 256>>>();

    // fused tensor-core GEMM (2 tiles/block) + one-pass bucketed fill
    k_gemm_fill<<<FUSED_BLOCKS, 256>>>(x, W, ei);

    // dinv + in-place fp16 prescale
    k_scale<<<(N_NODES * 32 + 255) / 256, 256>>>();

    // fused gather + self-loop + bias: one warp per node
    const int gather_blocks = (N_NODES * 32 + 255) / 256;
    k_gather<<<gather_blocks, 256>>>(b, y);
}